// round 13
// baseline (speedup 1.0000x reference)
#include <cuda_runtime.h>
#include <cuda_fp16.h>
#include <cstdint>

#define GM 8192
#define GN 1024
#define GK 1024
#define SEQ 2048
#define NHEAD 16
#define HDIM 64
#define BATCH 4

// fp16 staging buffers (allocation-free rule: __device__ globals)
__device__ __half g_Xh[(size_t)GM * GK];
__device__ __half g_Wqh[(size_t)GN * GK];
__device__ __half g_Wkh[(size_t)GN * GK];
__device__ __half g_Wvh[(size_t)GN * GK];
__device__ __half g_Woh[(size_t)GN * GK];
__device__ __half g_Qh[(size_t)GM * GN];
__device__ __half g_Kh[(size_t)GM * GN];
__device__ __half g_Vh[(size_t)GM * GN];
__device__ __half g_Ch[(size_t)GM * GN];

// ---------------------------------------------------------------------------
// PTX helpers
// ---------------------------------------------------------------------------
__device__ __forceinline__ uint32_t smem_u32(const void* p) {
    return (uint32_t)__cvta_generic_to_shared(p);
}
#define SWZ(o) ((o) ^ (((o) >> 3) & 0x70))

__device__ __forceinline__ void cp16(uint32_t dst, const void* src) {
    asm volatile("cp.async.cg.shared.global [%0], [%1], 16;" :: "r"(dst), "l"(src));
}
__device__ __forceinline__ void cp_commit() {
    asm volatile("cp.async.commit_group;");
}
template <int N>
__device__ __forceinline__ void cp_wait() {
    asm volatile("cp.async.wait_group %0;" :: "n"(N));
}

__device__ __forceinline__ void ldsm4(uint32_t& a, uint32_t& b, uint32_t& c,
                                      uint32_t& d, uint32_t addr) {
    asm volatile("ldmatrix.sync.aligned.m8n8.x4.shared.b16 {%0,%1,%2,%3}, [%4];"
                 : "=r"(a), "=r"(b), "=r"(c), "=r"(d) : "r"(addr));
}
__device__ __forceinline__ void ldsm4t(uint32_t& a, uint32_t& b, uint32_t& c,
                                       uint32_t& d, uint32_t addr) {
    asm volatile("ldmatrix.sync.aligned.m8n8.x4.trans.shared.b16 {%0,%1,%2,%3}, [%4];"
                 : "=r"(a), "=r"(b), "=r"(c), "=r"(d) : "r"(addr));
}

__device__ __forceinline__ void mma_h(float* c, const uint32_t* a,
                                      uint32_t b0, uint32_t b1) {
    asm volatile(
        "mma.sync.aligned.m16n8k16.row.col.f32.f16.f16.f32 "
        "{%0,%1,%2,%3}, {%4,%5,%6,%7}, {%8,%9}, {%0,%1,%2,%3};"
        : "+f"(c[0]), "+f"(c[1]), "+f"(c[2]), "+f"(c[3])
        : "r"(a[0]), "r"(a[1]), "r"(a[2]), "r"(a[3]), "r"(b0), "r"(b1));
}

// ---------------------------------------------------------------------------
// Fused fp32 -> fp16 rounding pre-pass (x + 4 weight matrices, one launch)
// ---------------------------------------------------------------------------
#define XN4 (GM * GK / 4)
#define WN4 (GN * GK / 4)

__global__ void f2h_all_kernel(const float* __restrict__ x,
                               const float* __restrict__ wq,
                               const float* __restrict__ wk,
                               const float* __restrict__ wv,
                               const float* __restrict__ wo)
{
    const int i = blockIdx.x * blockDim.x + threadIdx.x;
    const float* src;
    __half* dst;
    int idx;
    if (i < XN4) {
        src = x; dst = g_Xh; idx = i;
    } else {
        const int j = i - XN4;
        const int w = j / WN4;
        idx = j - w * WN4;
        switch (w) {
            case 0:  src = wq; dst = g_Wqh; break;
            case 1:  src = wk; dst = g_Wkh; break;
            case 2:  src = wv; dst = g_Wvh; break;
            default: src = wo; dst = g_Woh; break;
        }
    }
    float4 v = *(const float4*)(src + (size_t)idx * 4);
    __half2* o = (__half2*)dst + (size_t)idx * 2;
    o[0] = __floats2half2_rn(v.x, v.y);
    o[1] = __floats2half2_rn(v.z, v.w);
}

// ---------------------------------------------------------------------------
// GEMM tile body: one 128x64 output tile, full K sweep.
// 256 threads, 8 warps 2(M)x4(N), warp tile 64x16.
// 3-slot cp.async ring (A 16KB + B 8KB per stage), prefetch distance 2,
// ONE barrier per K-tile.
// ---------------------------------------------------------------------------
#define STG_A 16384
#define STG_B 8192
#define STG_SZ (STG_A + STG_B)    // 24576; 3 stages = 73728
#define NT_K 16                    // 1024 / 64

template <int OUT_HALF>
__device__ __forceinline__ void gemm_tile(const __half* __restrict__ A,
                                          const __half* __restrict__ B,
                                          const float* __restrict__ bias,
                                          void* __restrict__ Cout,
                                          int row0, int col0)
{
    extern __shared__ char smraw[];
    const int t    = threadIdx.x;
    const int lane = t & 31;
    const int warp = t >> 5;
    const int g    = lane >> 2;
    const int t4   = lane & 3;
    const int wm   = (warp >> 2) * 64;   // 0,64
    const int wn   = (warp & 3) * 16;    // 0,16,32,48
    const uint32_t smb = smem_u32(smraw);

    float acc[4][2][4];
#pragma unroll
    for (int mi = 0; mi < 4; mi++)
#pragma unroll
        for (int nf = 0; nf < 2; nf++)
#pragma unroll
            for (int r = 0; r < 4; r++) acc[mi][nf][r] = 0.f;

    const int lrow = t >> 3;   // 0..31
    const int lcb  = t & 7;    // 16B chunk

    auto load_stage = [&](int kt, int s) {
        const __half* Ag = A + (size_t)row0 * GK + kt * 64;
        const __half* Bg = B + (size_t)col0 * GK + kt * 64;
        const uint32_t as = smb + s * STG_SZ;
        const uint32_t bs = as + STG_A;
#pragma unroll
        for (int i = 0; i < 4; i++) {
            const int r = lrow + i * 32;
            cp16(as + SWZ(r * 128 + lcb * 16), Ag + (size_t)r * GK + lcb * 8);
        }
#pragma unroll
        for (int i = 0; i < 2; i++) {
            const int r = lrow + i * 32;
            cp16(bs + SWZ(r * 128 + lcb * 16), Bg + (size_t)r * GK + lcb * 8);
        }
        cp_commit();
    };

    load_stage(0, 0);
    load_stage(1, 1);

#pragma unroll 1
    for (int kt = 0; kt < NT_K; kt++) {
        const int s = kt % 3;
        if (kt < NT_K - 1) cp_wait<1>(); else cp_wait<0>();
        __syncthreads();
        if (kt + 2 < NT_K) load_stage(kt + 2, (kt + 2) % 3);

        const uint32_t as = smb + s * STG_SZ;
        const uint32_t bs = as + STG_A;

#pragma unroll
        for (int ks = 0; ks < 4; ks++) {
            const int k0 = ks * 16;
            uint32_t af[4][4], bf[2][2];
#pragma unroll
            for (int mi = 0; mi < 4; mi++) {
                const int r  = wm + mi * 16 + (lane & 7) + ((lane >> 3) & 1) * 8;
                const int cb = k0 * 2 + ((lane >> 4) & 1) * 16;
                ldsm4(af[mi][0], af[mi][1], af[mi][2], af[mi][3],
                      as + SWZ(r * 128 + cb));
            }
            {
                const int r  = wn + (lane & 7) + ((lane >> 4) & 1) * 8;
                const int cb = k0 * 2 + ((lane >> 3) & 1) * 16;
                uint32_t b0, b1, b2, b3;
                ldsm4(b0, b1, b2, b3, bs + SWZ(r * 128 + cb));
                bf[0][0] = b0; bf[0][1] = b1;
                bf[1][0] = b2; bf[1][1] = b3;
            }
#pragma unroll
            for (int mi = 0; mi < 4; mi++)
#pragma unroll
                for (int nf = 0; nf < 2; nf++)
                    mma_h(acc[mi][nf], af[mi], bf[nf][0], bf[nf][1]);
        }
    }

#pragma unroll
    for (int mi = 0; mi < 4; mi++) {
        const int row = row0 + wm + mi * 16 + g;
#pragma unroll
        for (int nf = 0; nf < 2; nf++) {
            const int col = col0 + wn + nf * 8 + 2 * t4;
            const float b0 = bias[col], b1 = bias[col + 1];
            const float v00 = acc[mi][nf][0] + b0, v01 = acc[mi][nf][1] + b1;
            const float v10 = acc[mi][nf][2] + b0, v11 = acc[mi][nf][3] + b1;
            if (OUT_HALF) {
                __half2* o = (__half2*)Cout;
                o[((size_t)row * GN + col) >> 1]       = __floats2half2_rn(v00, v01);
                o[((size_t)(row + 8) * GN + col) >> 1] = __floats2half2_rn(v10, v11);
            } else {
                float* o = (float*)Cout;
                *(float2*)(o + (size_t)row * GN + col)       = make_float2(v00, v01);
                *(float2*)(o + (size_t)(row + 8) * GN + col) = make_float2(v10, v11);
            }
        }
    }
    __syncthreads();   // protect smem ring before next tile's prologue
}

#define PERS_CTAS 296   // 148 SMs x 2 CTAs

// Persistent fused QKV: 3072 tiles (3 mats x 64 rowtiles x 16 coltiles).
__global__ __launch_bounds__(256, 2)
void gemm_qkv_kernel(const __half* __restrict__ A,
                     const float* __restrict__ bq,
                     const float* __restrict__ bk,
                     const float* __restrict__ bv)
{
    const int num_tiles = 3 * (GM / 128) * (GN / 64);   // 3072
#pragma unroll 1
    for (int tile = blockIdx.x; tile < num_tiles; tile += PERS_CTAS) {
        const int mat = tile >> 10;
        const int rem = tile & 1023;
        const int row0 = (rem >> 4) << 7;   // col fastest -> A panel reuse
        const int col0 = (rem & 15) << 6;
        const __half* B;
        const float* bias;
        __half* dst;
        switch (mat) {
            case 0:  B = g_Wqh; bias = bq; dst = g_Qh; break;
            case 1:  B = g_Wkh; bias = bk; dst = g_Kh; break;
            default: B = g_Wvh; bias = bv; dst = g_Vh; break;
        }
        gemm_tile<1>(A, B, bias, dst, row0, col0);
    }
}

// Persistent O-projection: 1024 tiles.
__global__ __launch_bounds__(256, 2)
void gemm_o_kernel(const __half* __restrict__ A,
                   const float* __restrict__ bias, float* __restrict__ Cout)
{
    const int num_tiles = (GM / 128) * (GN / 64);   // 1024
#pragma unroll 1
    for (int tile = blockIdx.x; tile < num_tiles; tile += PERS_CTAS) {
        const int row0 = (tile >> 4) << 7;
        const int col0 = (tile & 15) << 6;
        gemm_tile<0>(A, g_Woh, bias, Cout, row0, col0);
    }
}

// ---------------------------------------------------------------------------
// Flash attention, fp16 mma (fp32 acc), register-resident P, f16x2 exp.
// CTA = 64 queries x one (b,h), 4 warps x 16 q. 64-key tiles,
// 4-stage KV ring via cp.async, one __syncthreads per tile. 128 threads.
// Smem: Q 8KB @0 (region reserved to 16KB); KV stage s at 16384 + s*16384.
// smem request 81920 keeps exactly 2 CTAs/SM.
// ---------------------------------------------------------------------------
__global__ __launch_bounds__(128)
void attn_h_kernel(const __half* __restrict__ Q, const __half* __restrict__ K,
                   const __half* __restrict__ V, __half* __restrict__ O)
{
    extern __shared__ char smraw[];
    const int t    = threadIdx.x;
    const int lane = t & 31;
    const int warp = t >> 5;
    const int g    = lane >> 2;
    const int t4   = lane & 3;
    const int q0   = blockIdx.x * 64;
    const size_t base = (size_t)blockIdx.z * SEQ * GN + (size_t)blockIdx.y * HDIM;
    const uint32_t smb = smem_u32(smraw);

    const int lrow = t >> 3;   // 0..15
    const int lcb  = t & 7;

    auto load_kv = [&](int kt, int s) {
        const __half* Kg = K + base + (size_t)(kt * 64) * GN;
        const __half* Vg = V + base + (size_t)(kt * 64) * GN;
        const uint32_t ks = smb + 16384 + s * 16384;
        const uint32_t vs = ks + 8192;
#pragma unroll
        for (int i = 0; i < 4; i++) {
            const int r = lrow + i * 16;
            const uint32_t off = SWZ(r * 128 + lcb * 16);
            cp16(ks + off, Kg + (size_t)r * GN + lcb * 8);
            cp16(vs + off, Vg + (size_t)r * GN + lcb * 8);
        }
    };

    // Q: 64 rows
    {
        const __half* Qg = Q + base + (size_t)q0 * GN;
#pragma unroll
        for (int i = 0; i < 4; i++) {
            const int r = lrow + i * 16;
            cp16(smb + SWZ(r * 128 + lcb * 16), Qg + (size_t)r * GN + lcb * 8);
        }
    }
    load_kv(0, 0);
    cp_commit();
    load_kv(1, 1);
    cp_commit();
    load_kv(2, 2);
    cp_commit();

    cp_wait<2>();
    __syncthreads();

    // Hoist Q fragments: warp owns rows [warp*16, warp*16+16)
    uint32_t qa[4][4];
#pragma unroll
    for (int kf = 0; kf < 4; kf++) {
        const int r  = warp * 16 + (lane & 7) + ((lane >> 3) & 1) * 8;
        const int cb = kf * 32 + ((lane >> 4) & 1) * 16;
        ldsm4(qa[kf][0], qa[kf][1], qa[kf][2], qa[kf][3],
              smb + SWZ(r * 128 + cb));
    }

    float mrun[2], lrun[2];
    float o[8][4];
    mrun[0] = mrun[1] = -1e30f;
    lrun[0] = lrun[1] = 0.f;
#pragma unroll
    for (int nf = 0; nf < 8; nf++)
#pragma unroll
        for (int r = 0; r < 4; r++) o[nf][r] = 0.f;

    const float cexp = 0.125f * 1.44269504089f;
    const int NT = SEQ / 64;

#pragma unroll 1
    for (int kt = 0; kt < NT; kt++) {
        const int s = kt & 3;
        if (kt > 0) {
            if (kt <= NT - 3)      cp_wait<2>();
            else if (kt == NT - 2) cp_wait<1>();
            else                   cp_wait<0>();
            __syncthreads();
        }
        if (kt + 3 < NT) { load_kv(kt + 3, (kt + 3) & 3); cp_commit(); }

        const uint32_t ks = smb + 16384 + s * 16384;
        const uint32_t vs = ks + 8192;

        // S = Q K^T
        float s_[8][4];
#pragma unroll
        for (int nf = 0; nf < 8; nf++)
#pragma unroll
            for (int r = 0; r < 4; r++) s_[nf][r] = 0.f;

#pragma unroll
        for (int kf = 0; kf < 4; kf++) {
#pragma unroll
            for (int np = 0; np < 4; np++) {
                const int r  = np * 16 + (lane & 7) + ((lane >> 4) & 1) * 8;
                const int cb = kf * 32 + ((lane >> 3) & 1) * 16;
                uint32_t b0, b1, b2, b3;
                ldsm4(b0, b1, b2, b3, ks + SWZ(r * 128 + cb));
                mma_h(s_[np * 2],     qa[kf], b0, b1);
                mma_h(s_[np * 2 + 1], qa[kf], b2, b3);
            }
        }

        // Online softmax; P via ex2.approx.f16x2 into A-fragments
        uint32_t pa[4][4];
        {
            float mx0 = -1e30f, mx1 = -1e30f;
#pragma unroll
            for (int nf = 0; nf < 8; nf++) {
                mx0 = fmaxf(mx0, fmaxf(s_[nf][0], s_[nf][1]));
                mx1 = fmaxf(mx1, fmaxf(s_[nf][2], s_[nf][3]));
            }
            mx0 = fmaxf(mx0, __shfl_xor_sync(0xffffffffu, mx0, 1));
            mx0 = fmaxf(mx0, __shfl_xor_sync(0xffffffffu, mx0, 2));
            mx1 = fmaxf(mx1, __shfl_xor_sync(0xffffffffu, mx1, 1));
            mx1 = fmaxf(mx1, __shfl_xor_sync(0xffffffffu, mx1, 2));

            const float mn0 = fmaxf(mrun[0], mx0);
            const float mn1 = fmaxf(mrun[1], mx1);
            const float a0  = exp2f((mrun[0] - mn0) * cexp);
            const float a1  = exp2f((mrun[1] - mn1) * cexp);
            mrun[0] = mn0; mrun[1] = mn1;
            const float c0  = mn0 * cexp;
            const float c1  = mn1 * cexp;

            float rs0 = 0.f, rs1 = 0.f;
#pragma unroll
            for (int nf = 0; nf < 8; nf++) {
                const __half2 t01 = __floats2half2_rn(
                    fmaf(s_[nf][0], cexp, -c0),
                    fmaf(s_[nf][1], cexp, -c0));
                const __half2 t23 = __floats2half2_rn(
                    fmaf(s_[nf][2], cexp, -c1),
                    fmaf(s_[nf][3], cexp, -c1));
                const __half2 p01 = h2exp2(t01);
                const __half2 p23 = h2exp2(t23);
                const float2 f01 = __half22float2(p01);
                const float2 f23 = __half22float2(p23);
                rs0 += f01.x + f01.y;
                rs1 += f23.x + f23.y;
                const int kf = nf >> 1, hf = (nf & 1) * 2;
                pa[kf][hf]     = *(const uint32_t*)&p01;
                pa[kf][hf + 1] = *(const uint32_t*)&p23;
            }
            rs0 += __shfl_xor_sync(0xffffffffu, rs0, 1);
            rs0 += __shfl_xor_sync(0xffffffffu, rs0, 2);
            rs1 += __shfl_xor_sync(0xffffffffu, rs1, 1);
            rs1 += __shfl_xor_sync(0xffffffffu, rs1, 2);
            lrun[0] = lrun[0] * a0 + rs0;
            lrun[1] = lrun[1] * a1 + rs1;
#pragma unroll
            for (int nf = 0; nf < 8; nf++) {
                o[nf][0] *= a0; o[nf][1] *= a0;
                o[nf][2] *= a1; o[nf][3] *= a1;
            }
        }

        // O += P V (fp32 acc)
#pragma unroll
        for (int kf = 0; kf < 4; kf++) {
#pragma unroll
            for (int np = 0; np < 4; np++) {
                const int r  = kf * 16 + (lane & 7) + ((lane >> 3) & 1) * 8;
                const int cb = np * 32 + ((lane >> 4) & 1) * 16;
                uint32_t b0, b1, b2, b3;
                ldsm4t(b0, b1, b2, b3, vs + SWZ(r * 128 + cb));
                mma_h(o[np * 2],     pa[kf], b0, b1);
                mma_h(o[np * 2 + 1], pa[kf], b2, b3);
            }
        }
    }

    // Epilogue
    {
        const float inv0 = 1.f / lrun[0];
        const float inv1 = 1.f / lrun[1];
        const int row = q0 + warp * 16 + g;
#pragma unroll
        for (int nf = 0; nf < 8; nf++) {
            const int col = nf * 8 + 2 * t4;
            *(__half2*)(O + base + (size_t)row * GN + col) =
                __floats2half2_rn(o[nf][0] * inv0, o[nf][1] * inv0);
            *(__half2*)(O + base + (size_t)(row + 8) * GN + col) =
                __floats2half2_rn(o[nf][2] * inv1, o[nf][3] * inv1);
        }
    }
}

// ---------------------------------------------------------------------------
extern "C" void kernel_launch(void* const* d_in, const int* in_sizes, int n_in,
                              void* d_out, int out_size)
{
    const float* x  = (const float*)d_in[0];
    const float* Wq = (const float*)d_in[1];
    const float* bq = (const float*)d_in[2];
    const float* Wk = (const float*)d_in[3];
    const float* bk = (const float*)d_in[4];
    const float* Wv = (const float*)d_in[5];
    const float* bv = (const float*)d_in[6];
    const float* Wo = (const float*)d_in[7];
    const float* bo = (const float*)d_in[8];
    float* out = (float*)d_out;

    __half *xh, *qh, *kh, *vh, *ch;
    cudaGetSymbolAddress((void**)&xh, g_Xh);
    cudaGetSymbolAddress((void**)&qh, g_Qh);
    cudaGetSymbolAddress((void**)&kh, g_Kh);
    cudaGetSymbolAddress((void**)&vh, g_Vh);
    cudaGetSymbolAddress((void**)&ch, g_Ch);

    {
        const int total4 = XN4 + 4 * WN4;
        f2h_all_kernel<<<(total4 + 255) / 256, 256>>>(x, Wq, Wk, Wv, Wo);
    }

    const int gsm = 3 * STG_SZ;   // 73728
    cudaFuncSetAttribute(gemm_qkv_kernel,
                         cudaFuncAttributeMaxDynamicSharedMemorySize, gsm);
    cudaFuncSetAttribute(gemm_o_kernel,
                         cudaFuncAttributeMaxDynamicSharedMemorySize, gsm);

    gemm_qkv_kernel<<<PERS_CTAS, 256, gsm>>>(xh, bq, bk, bv);

    const int asm_ = 16384 + 4 * 16384;   // 81920 -> exactly 2 CTAs/SM
    cudaFuncSetAttribute(attn_h_kernel,
                         cudaFuncAttributeMaxDynamicSharedMemorySize, asm_);
    dim3 agrid(SEQ / 64, NHEAD, BATCH);
    attn_h_kernel<<<agrid, 128, asm_>>>(qh, kh, vh, ch);

    gemm_o_kernel<<<PERS_CTAS, 256, gsm>>>(ch, bo, out);
}

// round 16
// speedup vs baseline: 1.2564x; 1.2564x over previous
#include <cuda_runtime.h>
#include <cuda_fp16.h>
#include <cstdint>

#define GM 8192
#define GN 1024
#define GK 1024
#define SEQ 2048
#define NHEAD 16
#define HDIM 64
#define BATCH 4

// fp16 staging buffers (allocation-free rule: __device__ globals)
__device__ __half g_Xh[(size_t)GM * GK];
__device__ __half g_Wqh[(size_t)GN * GK];
__device__ __half g_Wkh[(size_t)GN * GK];
__device__ __half g_Wvh[(size_t)GN * GK];
__device__ __half g_Woh[(size_t)GN * GK];
__device__ __half g_Qh[(size_t)GM * GN];
__device__ __half g_Kh[(size_t)GM * GN];
__device__ __half g_Vh[(size_t)GM * GN];
__device__ __half g_Ch[(size_t)GM * GN];

// ---------------------------------------------------------------------------
// PTX helpers
// ---------------------------------------------------------------------------
__device__ __forceinline__ uint32_t smem_u32(const void* p) {
    return (uint32_t)__cvta_generic_to_shared(p);
}
#define SWZ(o) ((o) ^ (((o) >> 3) & 0x70))

__device__ __forceinline__ void cp16(uint32_t dst, const void* src) {
    asm volatile("cp.async.cg.shared.global [%0], [%1], 16;" :: "r"(dst), "l"(src));
}
__device__ __forceinline__ void cp_commit() {
    asm volatile("cp.async.commit_group;");
}
template <int N>
__device__ __forceinline__ void cp_wait() {
    asm volatile("cp.async.wait_group %0;" :: "n"(N));
}

__device__ __forceinline__ void ldsm4(uint32_t& a, uint32_t& b, uint32_t& c,
                                      uint32_t& d, uint32_t addr) {
    asm volatile("ldmatrix.sync.aligned.m8n8.x4.shared.b16 {%0,%1,%2,%3}, [%4];"
                 : "=r"(a), "=r"(b), "=r"(c), "=r"(d) : "r"(addr));
}
__device__ __forceinline__ void ldsm4t(uint32_t& a, uint32_t& b, uint32_t& c,
                                       uint32_t& d, uint32_t addr) {
    asm volatile("ldmatrix.sync.aligned.m8n8.x4.trans.shared.b16 {%0,%1,%2,%3}, [%4];"
                 : "=r"(a), "=r"(b), "=r"(c), "=r"(d) : "r"(addr));
}

__device__ __forceinline__ void mma_h(float* c, const uint32_t* a,
                                      uint32_t b0, uint32_t b1) {
    asm volatile(
        "mma.sync.aligned.m16n8k16.row.col.f32.f16.f16.f32 "
        "{%0,%1,%2,%3}, {%4,%5,%6,%7}, {%8,%9}, {%0,%1,%2,%3};"
        : "+f"(c[0]), "+f"(c[1]), "+f"(c[2]), "+f"(c[3])
        : "r"(a[0]), "r"(a[1]), "r"(a[2]), "r"(a[3]), "r"(b0), "r"(b1));
}

// ---------------------------------------------------------------------------
// Fused fp32 -> fp16 rounding pre-pass (x + 4 weight matrices, one launch)
// ---------------------------------------------------------------------------
#define XN4 (GM * GK / 4)
#define WN4 (GN * GK / 4)

__global__ void f2h_all_kernel(const float* __restrict__ x,
                               const float* __restrict__ wq,
                               const float* __restrict__ wk,
                               const float* __restrict__ wv,
                               const float* __restrict__ wo)
{
    const int i = blockIdx.x * blockDim.x + threadIdx.x;
    const float* src;
    __half* dst;
    int idx;
    if (i < XN4) {
        src = x; dst = g_Xh; idx = i;
    } else {
        const int j = i - XN4;
        const int w = j / WN4;
        idx = j - w * WN4;
        switch (w) {
            case 0:  src = wq; dst = g_Wqh; break;
            case 1:  src = wk; dst = g_Wkh; break;
            case 2:  src = wv; dst = g_Wvh; break;
            default: src = wo; dst = g_Woh; break;
        }
    }
    float4 v = *(const float4*)(src + (size_t)idx * 4);
    __half2* o = (__half2*)dst + (size_t)idx * 2;
    o[0] = __floats2half2_rn(v.x, v.y);
    o[1] = __floats2half2_rn(v.z, v.w);
}

// ---------------------------------------------------------------------------
// GEMM tile body: one 128x128 output tile, full K sweep.   (R12 config)
// 256 threads, 8 warps 2(M)x4(N), warp tile 64x32.
// 3-slot cp.async ring, prefetch distance 2, ONE barrier per K-tile.
// ---------------------------------------------------------------------------
#define STG_SZ 32768    // A 16KB + B 16KB per stage
#define NT_K 16         // 1024 / 64

template <int OUT_HALF>
__device__ __forceinline__ void gemm_tile(const __half* __restrict__ A,
                                          const __half* __restrict__ B,
                                          const float* __restrict__ bias,
                                          void* __restrict__ Cout,
                                          int row0, int col0)
{
    extern __shared__ char smraw[];
    const int t    = threadIdx.x;
    const int lane = t & 31;
    const int warp = t >> 5;
    const int g    = lane >> 2;
    const int t4   = lane & 3;
    const int wm   = (warp >> 2) * 64;
    const int wn   = (warp & 3) * 32;
    const uint32_t smb = smem_u32(smraw);

    float acc[4][4][4];
#pragma unroll
    for (int mi = 0; mi < 4; mi++)
#pragma unroll
        for (int nf = 0; nf < 4; nf++)
#pragma unroll
            for (int r = 0; r < 4; r++) acc[mi][nf][r] = 0.f;

    const int lrow = t >> 3;
    const int lcb  = t & 7;

    auto load_stage = [&](int kt, int s) {
        const __half* Ag = A + (size_t)row0 * GK + kt * 64;
        const __half* Bg = B + (size_t)col0 * GK + kt * 64;
        const uint32_t as = smb + s * STG_SZ;
        const uint32_t bs = as + 16384;
#pragma unroll
        for (int i = 0; i < 4; i++) {
            const int r = lrow + i * 32;
            const uint32_t off = SWZ(r * 128 + lcb * 16);
            cp16(as + off, Ag + (size_t)r * GK + lcb * 8);
            cp16(bs + off, Bg + (size_t)r * GK + lcb * 8);
        }
        cp_commit();
    };

    load_stage(0, 0);
    load_stage(1, 1);

#pragma unroll 1
    for (int kt = 0; kt < NT_K; kt++) {
        const int s = kt % 3;
        if (kt < NT_K - 1) cp_wait<1>(); else cp_wait<0>();
        __syncthreads();
        if (kt + 2 < NT_K) load_stage(kt + 2, (kt + 2) % 3);

        const uint32_t as = smb + s * STG_SZ;
        const uint32_t bs = as + 16384;

#pragma unroll
        for (int ks = 0; ks < 4; ks++) {
            const int k0 = ks * 16;
            uint32_t af[4][4], bf[4][2];
#pragma unroll
            for (int mi = 0; mi < 4; mi++) {
                const int r  = wm + mi * 16 + (lane & 7) + ((lane >> 3) & 1) * 8;
                const int cb = k0 * 2 + ((lane >> 4) & 1) * 16;
                ldsm4(af[mi][0], af[mi][1], af[mi][2], af[mi][3],
                      as + SWZ(r * 128 + cb));
            }
#pragma unroll
            for (int np = 0; np < 2; np++) {
                const int r  = wn + np * 16 + (lane & 7) + ((lane >> 4) & 1) * 8;
                const int cb = k0 * 2 + ((lane >> 3) & 1) * 16;
                uint32_t b0, b1, b2, b3;
                ldsm4(b0, b1, b2, b3, bs + SWZ(r * 128 + cb));
                bf[np * 2][0] = b0; bf[np * 2][1] = b1;
                bf[np * 2 + 1][0] = b2; bf[np * 2 + 1][1] = b3;
            }
#pragma unroll
            for (int mi = 0; mi < 4; mi++)
#pragma unroll
                for (int nf = 0; nf < 4; nf++)
                    mma_h(acc[mi][nf], af[mi], bf[nf][0], bf[nf][1]);
        }
    }

#pragma unroll
    for (int mi = 0; mi < 4; mi++) {
        const int row = row0 + wm + mi * 16 + g;
#pragma unroll
        for (int nf = 0; nf < 4; nf++) {
            const int col = col0 + wn + nf * 8 + 2 * t4;
            const float b0 = bias[col], b1 = bias[col + 1];
            const float v00 = acc[mi][nf][0] + b0, v01 = acc[mi][nf][1] + b1;
            const float v10 = acc[mi][nf][2] + b0, v11 = acc[mi][nf][3] + b1;
            if (OUT_HALF) {
                __half2* o = (__half2*)Cout;
                o[((size_t)row * GN + col) >> 1]       = __floats2half2_rn(v00, v01);
                o[((size_t)(row + 8) * GN + col) >> 1] = __floats2half2_rn(v10, v11);
            } else {
                float* o = (float*)Cout;
                *(float2*)(o + (size_t)row * GN + col)       = make_float2(v00, v01);
                *(float2*)(o + (size_t)(row + 8) * GN + col) = make_float2(v10, v11);
            }
        }
    }
    __syncthreads();   // protect smem ring before next tile's prologue
}

#define PERS_CTAS 296   // 148 SMs x 2 CTAs

// Persistent fused QKV: 1536 tiles (3 mats x 64 rows x 8 cols).
__global__ __launch_bounds__(256, 2)
void gemm_qkv_kernel(const __half* __restrict__ A,
                     const float* __restrict__ bq,
                     const float* __restrict__ bk,
                     const float* __restrict__ bv)
{
    const int num_tiles = 3 * (GM / 128) * (GN / 128);   // 1536
#pragma unroll 1
    for (int tile = blockIdx.x; tile < num_tiles; tile += PERS_CTAS) {
        const int mat = tile >> 9;
        const int rem = tile & 511;
        const int row0 = (rem >> 3) * 128;
        const int col0 = (rem & 7) * 128;
        const __half* B;
        const float* bias;
        __half* dst;
        switch (mat) {
            case 0:  B = g_Wqh; bias = bq; dst = g_Qh; break;
            case 1:  B = g_Wkh; bias = bk; dst = g_Kh; break;
            default: B = g_Wvh; bias = bv; dst = g_Vh; break;
        }
        gemm_tile<1>(A, B, bias, dst, row0, col0);
    }
}

// Persistent O-projection: 512 tiles.
__global__ __launch_bounds__(256, 2)
void gemm_o_kernel(const __half* __restrict__ A,
                   const float* __restrict__ bias, float* __restrict__ Cout)
{
    const int num_tiles = (GM / 128) * (GN / 128);   // 512
#pragma unroll 1
    for (int tile = blockIdx.x; tile < num_tiles; tile += PERS_CTAS) {
        const int row0 = (tile >> 3) * 128;
        const int col0 = (tile & 7) * 128;
        gemm_tile<0>(A, g_Woh, bias, Cout, row0, col0);
    }
}

// ---------------------------------------------------------------------------
// PERSISTENT flash attention, fp16 mma (fp32 acc), register-resident P.
// 296 CTAs loop over 1024 units of (128 queries x one (b,h)).
// Per unit: 4 warps x 32 q, 64-key tiles, 4-stage KV ring, one barrier/tile.
// Smem: Q 16KB @0; KV stage s at 16384 + s*16384. 81920 B -> 2 CTAs/SM.
// ---------------------------------------------------------------------------
__global__ __launch_bounds__(128)
void attn_h_kernel(const __half* __restrict__ Q, const __half* __restrict__ K,
                   const __half* __restrict__ V, __half* __restrict__ O)
{
    extern __shared__ char smraw[];
    const int t    = threadIdx.x;
    const int lane = t & 31;
    const int warp = t >> 5;
    const int g    = lane >> 2;
    const int t4   = lane & 3;
    const uint32_t smb = smem_u32(smraw);

    const int lrow = t >> 3;
    const int lcb  = t & 7;

    const int NUM_UNITS = (SEQ / 128) * NHEAD * BATCH;   // 1024
    const int NT = SEQ / 64;
    const float cexp = 0.125f * 1.44269504089f;

#pragma unroll 1
    for (int unit = blockIdx.x; unit < NUM_UNITS; unit += PERS_CTAS) {
        // decode: qt fastest, then h, then b
        const int qt = unit & 15;
        const int h  = (unit >> 4) & 15;
        const int b  = unit >> 8;
        const int q0 = qt * 128;
        const size_t base = (size_t)b * SEQ * GN + (size_t)h * HDIM;

        auto load_kv = [&](int kt, int s) {
            const __half* Kg = K + base + (size_t)(kt * 64) * GN;
            const __half* Vg = V + base + (size_t)(kt * 64) * GN;
            const uint32_t ks = smb + 16384 + s * 16384;
            const uint32_t vs = ks + 8192;
#pragma unroll
            for (int i = 0; i < 4; i++) {
                const int r = lrow + i * 16;
                const uint32_t off = SWZ(r * 128 + lcb * 16);
                cp16(ks + off, Kg + (size_t)r * GN + lcb * 8);
                cp16(vs + off, Vg + (size_t)r * GN + lcb * 8);
            }
        };

        // Prologue for this unit
        {
            const __half* Qg = Q + base + (size_t)q0 * GN;
#pragma unroll
            for (int i = 0; i < 8; i++) {
                const int r = lrow + i * 16;
                cp16(smb + SWZ(r * 128 + lcb * 16), Qg + (size_t)r * GN + lcb * 8);
            }
        }
        load_kv(0, 0);
        cp_commit();
        load_kv(1, 1);
        cp_commit();
        load_kv(2, 2);
        cp_commit();

        cp_wait<2>();
        __syncthreads();

        uint32_t qa[2][4][4];
#pragma unroll
        for (int mi = 0; mi < 2; mi++)
#pragma unroll
            for (int kf = 0; kf < 4; kf++) {
                const int r  = warp * 32 + mi * 16 + (lane & 7) + ((lane >> 3) & 1) * 8;
                const int cb = kf * 32 + ((lane >> 4) & 1) * 16;
                ldsm4(qa[mi][kf][0], qa[mi][kf][1], qa[mi][kf][2], qa[mi][kf][3],
                      smb + SWZ(r * 128 + cb));
            }

        float mrun[2][2], lrun[2][2];
        float o[2][8][4];
#pragma unroll
        for (int mi = 0; mi < 2; mi++) {
            mrun[mi][0] = mrun[mi][1] = -1e30f;
            lrun[mi][0] = lrun[mi][1] = 0.f;
#pragma unroll
            for (int nf = 0; nf < 8; nf++)
#pragma unroll
                for (int r = 0; r < 4; r++) o[mi][nf][r] = 0.f;
        }

#pragma unroll 1
        for (int kt = 0; kt < NT; kt++) {
            const int s = kt & 3;
            if (kt > 0) {
                if (kt <= NT - 3)      cp_wait<2>();
                else if (kt == NT - 2) cp_wait<1>();
                else                   cp_wait<0>();
                __syncthreads();
            }
            if (kt + 3 < NT) { load_kv(kt + 3, (kt + 3) & 3); cp_commit(); }

            const uint32_t ks = smb + 16384 + s * 16384;
            const uint32_t vs = ks + 8192;

            float s_[2][8][4];
#pragma unroll
            for (int mi = 0; mi < 2; mi++)
#pragma unroll
                for (int nf = 0; nf < 8; nf++)
#pragma unroll
                    for (int r = 0; r < 4; r++) s_[mi][nf][r] = 0.f;

#pragma unroll
            for (int kf = 0; kf < 4; kf++) {
#pragma unroll
                for (int np = 0; np < 4; np++) {
                    const int r  = np * 16 + (lane & 7) + ((lane >> 4) & 1) * 8;
                    const int cb = kf * 32 + ((lane >> 3) & 1) * 16;
                    uint32_t b0, b1, b2, b3;
                    ldsm4(b0, b1, b2, b3, ks + SWZ(r * 128 + cb));
#pragma unroll
                    for (int mi = 0; mi < 2; mi++) {
                        mma_h(s_[mi][np * 2],     qa[mi][kf], b0, b1);
                        mma_h(s_[mi][np * 2 + 1], qa[mi][kf], b2, b3);
                    }
                }
            }

            uint32_t pa[2][4][4];
#pragma unroll
            for (int mi = 0; mi < 2; mi++) {
                float mx0 = -1e30f, mx1 = -1e30f;
#pragma unroll
                for (int nf = 0; nf < 8; nf++) {
                    mx0 = fmaxf(mx0, fmaxf(s_[mi][nf][0], s_[mi][nf][1]));
                    mx1 = fmaxf(mx1, fmaxf(s_[mi][nf][2], s_[mi][nf][3]));
                }
                mx0 = fmaxf(mx0, __shfl_xor_sync(0xffffffffu, mx0, 1));
                mx0 = fmaxf(mx0, __shfl_xor_sync(0xffffffffu, mx0, 2));
                mx1 = fmaxf(mx1, __shfl_xor_sync(0xffffffffu, mx1, 1));
                mx1 = fmaxf(mx1, __shfl_xor_sync(0xffffffffu, mx1, 2));

                const float mn0 = fmaxf(mrun[mi][0], mx0);
                const float mn1 = fmaxf(mrun[mi][1], mx1);
                const float a0  = exp2f((mrun[mi][0] - mn0) * cexp);
                const float a1  = exp2f((mrun[mi][1] - mn1) * cexp);
                mrun[mi][0] = mn0; mrun[mi][1] = mn1;
                const float c0  = mn0 * cexp;
                const float c1  = mn1 * cexp;

                float rs0 = 0.f, rs1 = 0.f;
#pragma unroll
                for (int nf = 0; nf < 8; nf++) {
                    const __half2 t01 = __floats2half2_rn(
                        fmaf(s_[mi][nf][0], cexp, -c0),
                        fmaf(s_[mi][nf][1], cexp, -c0));
                    const __half2 t23 = __floats2half2_rn(
                        fmaf(s_[mi][nf][2], cexp, -c1),
                        fmaf(s_[mi][nf][3], cexp, -c1));
                    const __half2 p01 = h2exp2(t01);
                    const __half2 p23 = h2exp2(t23);
                    const float2 f01 = __half22float2(p01);
                    const float2 f23 = __half22float2(p23);
                    rs0 += f01.x + f01.y;
                    rs1 += f23.x + f23.y;
                    const int kf = nf >> 1, hf = (nf & 1) * 2;
                    pa[mi][kf][hf]     = *(const uint32_t*)&p01;
                    pa[mi][kf][hf + 1] = *(const uint32_t*)&p23;
                }
                rs0 += __shfl_xor_sync(0xffffffffu, rs0, 1);
                rs0 += __shfl_xor_sync(0xffffffffu, rs0, 2);
                rs1 += __shfl_xor_sync(0xffffffffu, rs1, 1);
                rs1 += __shfl_xor_sync(0xffffffffu, rs1, 2);
                lrun[mi][0] = lrun[mi][0] * a0 + rs0;
                lrun[mi][1] = lrun[mi][1] * a1 + rs1;
#pragma unroll
                for (int nf = 0; nf < 8; nf++) {
                    o[mi][nf][0] *= a0; o[mi][nf][1] *= a0;
                    o[mi][nf][2] *= a1; o[mi][nf][3] *= a1;
                }
            }

#pragma unroll
            for (int kf = 0; kf < 4; kf++) {
#pragma unroll
                for (int np = 0; np < 4; np++) {
                    const int r  = kf * 16 + (lane & 7) + ((lane >> 3) & 1) * 8;
                    const int cb = np * 32 + ((lane >> 4) & 1) * 16;
                    uint32_t b0, b1, b2, b3;
                    ldsm4t(b0, b1, b2, b3, vs + SWZ(r * 128 + cb));
#pragma unroll
                    for (int mi = 0; mi < 2; mi++) {
                        mma_h(o[mi][np * 2],     pa[mi][kf], b0, b1);
                        mma_h(o[mi][np * 2 + 1], pa[mi][kf], b2, b3);
                    }
                }
            }
        }

        // Epilogue for this unit
#pragma unroll
        for (int mi = 0; mi < 2; mi++) {
            const float inv0 = 1.f / lrun[mi][0];
            const float inv1 = 1.f / lrun[mi][1];
            const int row = q0 + warp * 32 + mi * 16 + g;
#pragma unroll
            for (int nf = 0; nf < 8; nf++) {
                const int col = nf * 8 + 2 * t4;
                *(__half2*)(O + base + (size_t)row * GN + col) =
                    __floats2half2_rn(o[mi][nf][0] * inv0, o[mi][nf][1] * inv0);
                *(__half2*)(O + base + (size_t)(row + 8) * GN + col) =
                    __floats2half2_rn(o[mi][nf][2] * inv1, o[mi][nf][3] * inv1);
            }
        }
        __syncthreads();   // all reads of the smem ring done before next unit
    }
}

// ---------------------------------------------------------------------------
extern "C" void kernel_launch(void* const* d_in, const int* in_sizes, int n_in,
                              void* d_out, int out_size)
{
    const float* x  = (const float*)d_in[0];
    const float* Wq = (const float*)d_in[1];
    const float* bq = (const float*)d_in[2];
    const float* Wk = (const float*)d_in[3];
    const float* bk = (const float*)d_in[4];
    const float* Wv = (const float*)d_in[5];
    const float* bv = (const float*)d_in[6];
    const float* Wo = (const float*)d_in[7];
    const float* bo = (const float*)d_in[8];
    float* out = (float*)d_out;

    __half *xh, *qh, *kh, *vh, *ch;
    cudaGetSymbolAddress((void**)&xh, g_Xh);
    cudaGetSymbolAddress((void**)&qh, g_Qh);
    cudaGetSymbolAddress((void**)&kh, g_Kh);
    cudaGetSymbolAddress((void**)&vh, g_Vh);
    cudaGetSymbolAddress((void**)&ch, g_Ch);

    {
        const int total4 = XN4 + 4 * WN4;
        f2h_all_kernel<<<(total4 + 255) / 256, 256>>>(x, Wq, Wk, Wv, Wo);
    }

    const int gsm = 3 * STG_SZ;   // 98304
    cudaFuncSetAttribute(gemm_qkv_kernel,
                         cudaFuncAttributeMaxDynamicSharedMemorySize, gsm);
    cudaFuncSetAttribute(gemm_o_kernel,
                         cudaFuncAttributeMaxDynamicSharedMemorySize, gsm);

    gemm_qkv_kernel<<<PERS_CTAS, 256, gsm>>>(xh, bq, bk, bv);

    const int asm_ = 16384 + 4 * 16384;   // 81920 -> 2 CTAs/SM
    cudaFuncSetAttribute(attn_h_kernel,
                         cudaFuncAttributeMaxDynamicSharedMemorySize, asm_);
    attn_h_kernel<<<PERS_CTAS, 128, asm_>>>(qh, kh, vh, ch);

    gemm_o_kernel<<<PERS_CTAS, 256, gsm>>>(ch, bo, out);
}